// round 16
// baseline (speedup 1.0000x reference)
#include <cuda_runtime.h>
#include <cuda_fp16.h>
#include <cstdint>

// ---------------------------------------------------------------------------
// BigramTransformer forward — fp16 HMMA GEMMs (fp32 accum), fp16 qkv,
// fused-LN epilogues, high-occupancy attention.
// B=2048 T=64 D=128 H=4 HD=32 L=6 V=256 DFF=512
// ---------------------------------------------------------------------------

#define Bc   2048
#define Tc   64
#define Dc   128
#define Hc   4
#define HDc  32
#define Lc   6
#define Vc   256
#define DFFc 512
#define NTOK (Bc * Tc)          /* 131072 */
#define QKVC (3 * Dc)           /* 384    */

// ------------------------- scratch (device globals) ------------------------
__device__ float  g_x  [(size_t)NTOK * Dc];
__device__ __half g_qkv[(size_t)NTOK * QKVC];
__device__ __half g_hh [(size_t)NTOK * Dc];
__device__ __half g_ah [(size_t)NTOK * Dc];
__device__ __half g_mh [(size_t)NTOK * DFFc];
// transposed fp16 weights [N,K]
__device__ __half g_wqkv[Lc * QKVC * Dc];
__device__ __half g_wo  [Lc * Dc * Dc];
__device__ __half g_w1  [Lc * DFFc * Dc];
__device__ __half g_w2  [Lc * Dc * DFFc];
__device__ __half g_whd [Vc * Dc];

// ------------------------- helpers ------------------------------------------
__device__ __forceinline__ uint32_t smem_u32(const void* p) {
    uint32_t a;
    asm("{ .reg .u64 t; cvta.to.shared.u64 t, %1; cvt.u32.u64 %0, t; }"
        : "=r"(a) : "l"(p));
    return a;
}
__device__ __forceinline__ void h2_store(float v0, float v1, __half* p) {
    *(__half2*)p = __floats2half2_rn(v0, v1);
}

#define LDMX4(r0, r1, r2, r3, a)                                            \
    asm volatile("ldmatrix.sync.aligned.m8n8.x4.shared.b16 {%0,%1,%2,%3}, [%4];" \
                 : "=r"(r0), "=r"(r1), "=r"(r2), "=r"(r3) : "r"(a))

#define MMA(d, a0, a1, a2, a3, b0v, b1v)                                    \
    asm volatile("mma.sync.aligned.m16n8k16.row.col.f32.f16.f16.f32 "       \
                 "{%0,%1,%2,%3}, {%4,%5,%6,%7}, {%8,%9}, {%0,%1,%2,%3};"    \
                 : "+f"((d)[0]), "+f"((d)[1]), "+f"((d)[2]), "+f"((d)[3])   \
                 : "r"(a0), "r"(a1), "r"(a2), "r"(a3), "r"(b0v), "r"(b1v))

#define CP_ASYNC16(dst, src)                                                \
    asm volatile("cp.async.cg.shared.global [%0], [%1], 16;"                \
                 :: "r"(dst), "l"(src))
#define CP_COMMIT() asm volatile("cp.async.commit_group;" ::: "memory")
#define CP_WAIT(n)  asm volatile("cp.async.wait_group %0;" :: "n"(n) : "memory")

// ------------------------- weight conversion --------------------------------
__global__ void convw_kernel(const float* __restrict__ W,
                             __half* __restrict__ oh, int K, int N)
{
    const size_t base = (size_t)blockIdx.y * K * N;
    int i = blockIdx.x * 256 + threadIdx.x;
    if (i >= K * N) return;
    int k = i / N, n = i % N;
    oh[base + (size_t)n * K + k] = __float2half(W[base + i]);
}

__global__ void convqkv_kernel(const float* __restrict__ Wq,
                               const float* __restrict__ Wk,
                               const float* __restrict__ Wv,
                               __half* __restrict__ oh)
{
    int i = blockIdx.x * 256 + threadIdx.x;
    const int total = Lc * Hc * Dc * HDc;
    if (i >= total) return;
    int e = i % HDc;
    int d = (i / HDc) % Dc;
    int h = (i / (HDc * Dc)) % Hc;
    int l = i / (HDc * Dc * Hc);
    int src = ((l * Hc + h) * Dc + d) * HDc + e;
    const int col = h * HDc + e;
    oh[((size_t)l * QKVC + col) * Dc + d]          = __float2half(Wq[src]);
    oh[((size_t)l * QKVC + Dc + col) * Dc + d]     = __float2half(Wk[src]);
    oh[((size_t)l * QKVC + 2 * Dc + col) * Dc + d] = __float2half(Wv[src]);
}

// ------------------------- embedding + first LN (warp / token) --------------
__global__ __launch_bounds__(256) void embed_ln_kernel(
    const int* __restrict__ idx,
    const float* __restrict__ tok, const float* __restrict__ pos,
    float* __restrict__ xout, __half* __restrict__ oh,
    const float* __restrict__ gam, const float* __restrict__ bet)
{
    const int warp = threadIdx.x >> 5;
    const int lane = threadIdx.x & 31;
    const size_t n = (size_t)blockIdx.x * 8 + warp;
    const int t = (int)(n & (Tc - 1));
    const int v = idx[n];

    const float4 tv = ((const float4*)(tok + (size_t)v * Dc))[lane];
    const float4 pv = ((const float4*)(pos + (size_t)t * Dc))[lane];
    float4 x = make_float4(tv.x + pv.x, tv.y + pv.y, tv.z + pv.z, tv.w + pv.w);
    ((float4*)(xout + n * Dc))[lane] = x;

    float s = x.x + x.y + x.z + x.w;
    #pragma unroll
    for (int o = 16; o > 0; o >>= 1) s += __shfl_xor_sync(0xffffffffu, s, o);
    const float mean = s * (1.0f / Dc);

    float4 c = make_float4(x.x - mean, x.y - mean, x.z - mean, x.w - mean);
    float q = c.x * c.x + c.y * c.y + c.z * c.z + c.w * c.w;
    #pragma unroll
    for (int o = 16; o > 0; o >>= 1) q += __shfl_xor_sync(0xffffffffu, q, o);
    const float r = rsqrtf(q * (1.0f / Dc) + 1e-5f);

    const float4 g = ((const float4*)gam)[lane];
    const float4 b = ((const float4*)bet)[lane];
    h2_store(c.x * r * g.x + b.x, c.y * r * g.y + b.y, oh + n * Dc + lane * 4);
    h2_store(c.z * r * g.z + b.z, c.w * r * g.w + b.w, oh + n * Dc + lane * 4 + 2);
}

// ------------------------- fp16 HMMA GEMM (K-chunk 64, 2-stage pipeline) ----
#define TROWB 144
#define TILEB (128 * TROWB)
#define STAGEB (2 * TILEB)
#define HGEMM_SMEM (2 * STAGEB)

__global__ __launch_bounds__(256, 2) void hgemm_kernel(
    const __half* __restrict__ A, const __half* __restrict__ B,
    const float* __restrict__ bias, const float* __restrict__ res,
    float* __restrict__ outf, __half* __restrict__ outh,
    const float* __restrict__ lnG, const float* __restrict__ lnB,
    int M, int N, int K, int relu)
{
    extern __shared__ char smem[];
    const uint32_t sb = smem_u32(smem);

    const int tid = threadIdx.x;
    const int w   = tid >> 5;
    const int l   = tid & 31;
    const int wm  = w & 1;
    const int wn  = w >> 1;
    const int m0  = blockIdx.y * 128;
    const int n0  = blockIdx.x * 128;

    const int g    = l >> 3;
    const int idx  = l & 7;
    const int lrow = (g & 1) * 8 + idx;
    const int g2   = (g >> 1) * 16;

    const uint32_t arow = (uint32_t)(wm * 64 + lrow) * TROWB + g2;
    const uint32_t brow = (uint32_t)(wn * 32 + lrow) * TROWB + g2;

    const __half* Asrc = A + (size_t)m0 * K;
    const __half* Bsrc = B + (size_t)n0 * K;

    const int nstep = K >> 6;

    auto stage = [&](int c) {
        const int ck = c << 6;
        const uint32_t base = sb + (uint32_t)(c & 1) * STAGEB;
        #pragma unroll
        for (int i = tid; i < 1024; i += 256) {
            const int r  = i >> 3;
            const int c8 = i & 7;
            CP_ASYNC16(base + r * TROWB + c8 * 16,
                       Asrc + (size_t)r * K + ck + c8 * 8);
        }
        #pragma unroll
        for (int i = tid; i < 1024; i += 256) {
            const int r  = i >> 3;
            const int c8 = i & 7;
            CP_ASYNC16(base + TILEB + r * TROWB + c8 * 16,
                       Bsrc + (size_t)r * K + ck + c8 * 8);
        }
        CP_COMMIT();
    };

    float acc[4][4][4] = {};

    stage(0);
    for (int c = 0; c < nstep; c++) {
        if (c + 1 < nstep) {
            stage(c + 1);
            CP_WAIT(1);
        } else {
            CP_WAIT(0);
        }
        __syncthreads();

        const uint32_t AHo = sb + (uint32_t)(c & 1) * STAGEB;
        const uint32_t BHo = AHo + TILEB;

        #pragma unroll
        for (int ks = 0; ks < 4; ks++) {
            const uint32_t kb = ks * 32;
            uint32_t bh_[2][4];
            #pragma unroll
            for (int p = 0; p < 2; p++) {
                const uint32_t bo = brow + p * (16 * TROWB) + kb;
                LDMX4(bh_[p][0], bh_[p][1], bh_[p][2], bh_[p][3], BHo + bo);
            }
            #pragma unroll
            for (int mt = 0; mt < 4; mt++) {
                const uint32_t ao = arow + mt * (16 * TROWB) + kb;
                uint32_t a0, a1, a2, a3;
                LDMX4(a0, a1, a2, a3, AHo + ao);
                #pragma unroll
                for (int nt = 0; nt < 4; nt++) {
                    const int p = nt >> 1, q = nt & 1;
                    MMA(acc[mt][nt], a0, a1, a2, a3, bh_[p][q], bh_[p][q + 2]);
                }
            }
        }
        __syncthreads();
    }

    const int gr = l >> 2;
    const int gc = (l & 3) * 2;

    if (lnG) {
        // ---- fused epilogue: bias + residual + LN over the 128-wide row ----
        float* sums  = (float*)smem;
        float* sumsq = (float*)smem + 512;

        #pragma unroll
        for (int mt = 0; mt < 4; mt++) {
            #pragma unroll
            for (int h = 0; h < 2; h++) {
                const int r64 = wm * 64 + mt * 16 + gr + h * 8;
                const size_t row = (size_t)m0 + r64;
                float s = 0.f, q = 0.f;
                #pragma unroll
                for (int nt = 0; nt < 4; nt++) {
                    const int n = wn * 32 + nt * 8 + gc;
                    float v0 = acc[mt][nt][h * 2];
                    float v1 = acc[mt][nt][h * 2 + 1];
                    const float2 bb = *(const float2*)(bias + n);
                    v0 += bb.x; v1 += bb.y;
                    const float2 rr = *(const float2*)(res + row * Dc + n);
                    v0 += rr.x; v1 += rr.y;
                    acc[mt][nt][h * 2]     = v0;
                    acc[mt][nt][h * 2 + 1] = v1;
                    *(float2*)(outf + row * Dc + n) = make_float2(v0, v1);
                    s += v0 + v1;
                    q += v0 * v0 + v1 * v1;
                }
                s += __shfl_xor_sync(0xffffffffu, s, 1);
                s += __shfl_xor_sync(0xffffffffu, s, 2);
                q += __shfl_xor_sync(0xffffffffu, q, 1);
                q += __shfl_xor_sync(0xffffffffu, q, 2);
                if ((l & 3) == 0) {
                    sums [r64 * 4 + wn] = s;
                    sumsq[r64 * 4 + wn] = q;
                }
            }
        }
        __syncthreads();
        #pragma unroll
        for (int mt = 0; mt < 4; mt++) {
            #pragma unroll
            for (int h = 0; h < 2; h++) {
                const int r64 = wm * 64 + mt * 16 + gr + h * 8;
                const size_t row = (size_t)m0 + r64;
                float S = sums[r64 * 4] + sums[r64 * 4 + 1]
                        + sums[r64 * 4 + 2] + sums[r64 * 4 + 3];
                float Q = sumsq[r64 * 4] + sumsq[r64 * 4 + 1]
                        + sumsq[r64 * 4 + 2] + sumsq[r64 * 4 + 3];
                const float mean = S * (1.0f / Dc);
                const float var  = Q * (1.0f / Dc) - mean * mean;
                const float rst  = rsqrtf(var + 1e-5f);
                #pragma unroll
                for (int nt = 0; nt < 4; nt++) {
                    const int n = wn * 32 + nt * 8 + gc;
                    const float2 gg = *(const float2*)(lnG + n);
                    const float2 bb = *(const float2*)(lnB + n);
                    const float v0 = acc[mt][nt][h * 2];
                    const float v1 = acc[mt][nt][h * 2 + 1];
                    h2_store((v0 - mean) * rst * gg.x + bb.x,
                             (v1 - mean) * rst * gg.y + bb.y,
                             outh + row * Dc + n);
                }
            }
        }
        return;
    }

    // ---- plain epilogue ----
    #pragma unroll
    for (int mt = 0; mt < 4; mt++) {
        #pragma unroll
        for (int h = 0; h < 2; h++) {
            const size_t row = (size_t)m0 + wm * 64 + mt * 16 + gr + h * 8;
            #pragma unroll
            for (int nt = 0; nt < 4; nt++) {
                const int n = n0 + wn * 32 + nt * 8 + gc;
                float v0 = acc[mt][nt][h * 2];
                float v1 = acc[mt][nt][h * 2 + 1];
                if (bias) {
                    const float2 bb = *(const float2*)(bias + n);
                    v0 += bb.x; v1 += bb.y;
                }
                if (relu) { v0 = fmaxf(v0, 0.f); v1 = fmaxf(v1, 0.f); }
                if (outh) {
                    h2_store(v0, v1, outh + row * N + n);
                } else {
                    *(float2*)(outf + row * N + n) = make_float2(v0, v1);
                }
            }
        }
    }
}

// ------------------------- attention: 4 threads per row, fp16 qkv -----------
// __launch_bounds__(256,5): cap regs (~51) so smem (45KB) is the occupancy
// limit (5 blocks/SM), not registers.  q kept in smem (j-outer loop) to fit.
#define QKP 36
#define WMP 68
__global__ __launch_bounds__(256, 5) void attn_kernel(const __half* __restrict__ qkv,
                                                      __half* __restrict__ oh)
{
    __shared__ float qs[Tc][QKP];
    __shared__ float ks[Tc][QKP];
    __shared__ float vs[Tc][QKP];
    __shared__ float wm[Tc][WMP];

    const int bh  = blockIdx.x;
    const int b   = bh >> 2;
    const int h   = bh & 3;
    const int tid = threadIdx.x;

    // load q,k,v (fp16 -> fp32 smem): 3 mats x 64 rows x 4 uint4 (8 halves)
    for (int i = tid; i < 768; i += 256) {
        const int mat = i >> 8;
        const int r   = (i >> 2) & 63;
        const int j   = i & 3;
        const uint4 v = *(const uint4*)(qkv + ((size_t)(b * Tc + r)) * QKVC
                                        + mat * Dc + h * HDc + j * 8);
        const __half2* hp = (const __half2*)&v;
        float* dst = (mat == 0) ? &qs[r][8 * j] : (mat == 1) ? &ks[r][8 * j]
                                                             : &vs[r][8 * j];
        const float2 f0 = __half22float2(hp[0]);
        const float2 f1 = __half22float2(hp[1]);
        const float2 f2 = __half22float2(hp[2]);
        const float2 f3 = __half22float2(hp[3]);
        dst[0] = f0.x; dst[1] = f0.y; dst[2] = f1.x; dst[3] = f1.y;
        dst[4] = f2.x; dst[5] = f2.y; dst[6] = f3.x; dst[7] = f3.y;
    }
    __syncthreads();

    const int row = tid >> 2;
    const int sub = tid & 3;
    const float scale = 0.17677669529663687f;

    // scores: j-outer so q lives in 4 regs; per-i accumulation order is
    // still j-ascending (numerics identical to previous revision).
    float wv[16] = {};
    #pragma unroll
    for (int j = 0; j < HDc; j += 4) {
        const float4 qf = *(const float4*)&qs[row][j];
        #pragma unroll
        for (int i = 0; i < 16; i++) {
            const int s = sub + 4 * i;
            const float4 kf = *(const float4*)&ks[s][j];
            float d = wv[i];
            d = fmaf(qf.x, kf.x, d);
            d = fmaf(qf.y, kf.y, d);
            d = fmaf(qf.z, kf.z, d);
            d = fmaf(qf.w, kf.w, d);
            wv[i] = d;
        }
    }

    float mx = -1e30f;
    #pragma unroll
    for (int i = 0; i < 16; i++) {
        const int s = sub + 4 * i;
        wv[i] *= scale;
        if (s <= row) mx = fmaxf(mx, wv[i]);
    }
    mx = fmaxf(mx, __shfl_xor_sync(0xffffffffu, mx, 1));
    mx = fmaxf(mx, __shfl_xor_sync(0xffffffffu, mx, 2));

    float sum = 0.f;
    #pragma unroll
    for (int i = 0; i < 16; i++) {
        const int s = sub + 4 * i;
        const float e = (s <= row) ? __expf(wv[i] - mx) : 0.f;
        wv[i] = e;
        sum += e;
    }
    sum += __shfl_xor_sync(0xffffffffu, sum, 1);
    sum += __shfl_xor_sync(0xffffffffu, sum, 2);
    const float inv = 1.f / sum;

    #pragma unroll
    for (int i = 0; i < 16; i++)
        wm[row][sub + 4 * i] = wv[i] * inv;
    __syncthreads();

    const int d0 = sub * 8;
    float acc[8] = {};
    for (int s = 0; s <= row; s++) {
        const float wgt = wm[row][s];
        const float4 v0 = *(const float4*)&vs[s][d0];
        const float4 v1 = *(const float4*)&vs[s][d0 + 4];
        acc[0] = fmaf(wgt, v0.x, acc[0]);
        acc[1] = fmaf(wgt, v0.y, acc[1]);
        acc[2] = fmaf(wgt, v0.z, acc[2]);
        acc[3] = fmaf(wgt, v0.w, acc[3]);
        acc[4] = fmaf(wgt, v1.x, acc[4]);
        acc[5] = fmaf(wgt, v1.y, acc[5]);
        acc[6] = fmaf(wgt, v1.z, acc[6]);
        acc[7] = fmaf(wgt, v1.w, acc[7]);
    }

    const size_t base = ((size_t)(b * Tc + row)) * Dc + h * HDc + d0;
    #pragma unroll
    for (int j = 0; j < 8; j += 2)
        h2_store(acc[j], acc[j + 1], oh + base + j);
}

// ------------------------- launcher -----------------------------------------
extern "C" void kernel_launch(void* const* d_in, const int* in_sizes, int n_in,
                              void* d_out, int out_size)
{
    (void)in_sizes; (void)n_in; (void)out_size;
    const int*   idx  = (const int*)  d_in[0];
    const float* tok  = (const float*)d_in[1];
    const float* pos  = (const float*)d_in[2];
    const float* Wq   = (const float*)d_in[3];
    const float* Wk   = (const float*)d_in[4];
    const float* Wv   = (const float*)d_in[5];
    const float* Wo   = (const float*)d_in[6];
    const float* bo   = (const float*)d_in[7];
    const float* ln1g = (const float*)d_in[8];
    const float* ln1b = (const float*)d_in[9];
    const float* W1   = (const float*)d_in[10];
    const float* b1   = (const float*)d_in[11];
    const float* W2   = (const float*)d_in[12];
    const float* b2   = (const float*)d_in[13];
    const float* ln2g = (const float*)d_in[14];
    const float* ln2b = (const float*)d_in[15];
    const float* lnfg = (const float*)d_in[16];
    const float* lnfb = (const float*)d_in[17];
    const float* Wh   = (const float*)d_in[18];
    const float* bhd  = (const float*)d_in[19];
    float* out = (float*)d_out;

    float *x;
    __half *qkvh, *hh, *ah, *mh, *wq, *wo, *w1, *w2, *whd;
    cudaGetSymbolAddress((void**)&x,    g_x);
    cudaGetSymbolAddress((void**)&qkvh, g_qkv);
    cudaGetSymbolAddress((void**)&hh,   g_hh);
    cudaGetSymbolAddress((void**)&ah,   g_ah);
    cudaGetSymbolAddress((void**)&mh,   g_mh);
    cudaGetSymbolAddress((void**)&wq,   g_wqkv);
    cudaGetSymbolAddress((void**)&wo,   g_wo);
    cudaGetSymbolAddress((void**)&w1,   g_w1);
    cudaGetSymbolAddress((void**)&w2,   g_w2);
    cudaGetSymbolAddress((void**)&whd,  g_whd);

    cudaFuncSetAttribute(hgemm_kernel,
                         cudaFuncAttributeMaxDynamicSharedMemorySize, HGEMM_SMEM);

    const int MT = NTOK / 128;
    const dim3 gQKV(QKVC / 128, MT);
    const dim3 gD  (1,          MT);
    const dim3 gFF (DFFc / 128, MT);
    const dim3 gV  (Vc   / 128, MT);

    // Launch order interleaves weight conversion with layer-0 kernels so the
    // ncu capture window (-s 5 -c 1) lands on an hgemm launch (index 5 =
    // Wo GEMM with fused LN), giving GEMM-side profile data.
    convqkv_kernel<<<(Lc * Hc * Dc * HDc + 255) / 256, 256>>>(Wq, Wk, Wv, wq);        // 0
    embed_ln_kernel<<<NTOK / 8, 256>>>(idx, tok, pos, x, hh, ln1g, ln1b);             // 1
    hgemm_kernel<<<gQKV, 256, HGEMM_SMEM>>>(                                          // 2
        hh, wq, nullptr, nullptr, nullptr, qkvh, nullptr, nullptr,
        NTOK, QKVC, Dc, 0);
    attn_kernel<<<Bc * Hc, 256>>>(qkvh, ah);                                          // 3
    convw_kernel<<<dim3((Dc * Dc + 255) / 256, Lc), 256>>>(Wo, wo, Dc, Dc);           // 4
    hgemm_kernel<<<gD, 256, HGEMM_SMEM>>>(                                            // 5 <- profiled
        ah, wo, bo, x, x, hh, ln2g, ln2b, NTOK, Dc, Dc, 0);
    convw_kernel<<<dim3((Dc * DFFc + 255) / 256, Lc), 256>>>(W1, w1, Dc, DFFc);       // 6
    hgemm_kernel<<<gFF, 256, HGEMM_SMEM>>>(                                           // 7
        hh, w1, b1, nullptr, nullptr, mh, nullptr, nullptr, NTOK, DFFc, Dc, 1);
    convw_kernel<<<dim3((DFFc * Dc + 255) / 256, Lc), 256>>>(W2, w2, DFFc, Dc);       // 8
    hgemm_kernel<<<gD, 256, HGEMM_SMEM>>>(                                            // 9
        mh, w2, b2, x, x, hh, ln1g + Dc, ln1b + Dc, NTOK, Dc, DFFc, 0);
    convw_kernel<<<dim3((Dc * Vc + 255) / 256, 1), 256>>>(Wh, whd, Dc, Vc);           // 10

    for (int l = 1; l < Lc; l++) {
        hgemm_kernel<<<gQKV, 256, HGEMM_SMEM>>>(
            hh, wq + (size_t)l * QKVC * Dc,
            nullptr, nullptr, nullptr, qkvh, nullptr, nullptr,
            NTOK, QKVC, Dc, 0);
        attn_kernel<<<Bc * Hc, 256>>>(qkvh, ah);
        hgemm_kernel<<<gD, 256, HGEMM_SMEM>>>(
            ah, wo + (size_t)l * Dc * Dc,
            bo + l * Dc, x, x, hh, ln2g + l * Dc, ln2b + l * Dc,
            NTOK, Dc, Dc, 0);
        hgemm_kernel<<<gFF, 256, HGEMM_SMEM>>>(
            hh, w1 + (size_t)l * DFFc * Dc,
            b1 + l * DFFc, nullptr, nullptr, mh, nullptr, nullptr,
            NTOK, DFFc, Dc, 1);
        const float* ng = (l < Lc - 1) ? (ln1g + (l + 1) * Dc) : lnfg;
        const float* nb = (l < Lc - 1) ? (ln1b + (l + 1) * Dc) : lnfb;
        hgemm_kernel<<<gD, 256, HGEMM_SMEM>>>(
            mh, w2 + (size_t)l * Dc * DFFc,
            b2 + l * Dc, x, x, hh, ng, nb,
            NTOK, Dc, DFFc, 0);
    }

    hgemm_kernel<<<gV, 256, HGEMM_SMEM>>>(
        hh, whd, bhd, nullptr, out, nullptr, nullptr, nullptr,
        NTOK, Vc, Dc, 0);
}

// round 17
// speedup vs baseline: 1.4627x; 1.4627x over previous
#include <cuda_runtime.h>
#include <cuda_fp16.h>
#include <cstdint>

// ---------------------------------------------------------------------------
// BigramTransformer forward — fp16 HMMA GEMMs (fp32 accum), fp16 qkv,
// fused-LN epilogues, tensor-core attention (MMA scores + MMA output).
// B=2048 T=64 D=128 H=4 HD=32 L=6 V=256 DFF=512
// ---------------------------------------------------------------------------

#define Bc   2048
#define Tc   64
#define Dc   128
#define Hc   4
#define HDc  32
#define Lc   6
#define Vc   256
#define DFFc 512
#define NTOK (Bc * Tc)          /* 131072 */
#define QKVC (3 * Dc)           /* 384    */

// ------------------------- scratch (device globals) ------------------------
__device__ float  g_x  [(size_t)NTOK * Dc];
__device__ __half g_qkv[(size_t)NTOK * QKVC];
__device__ __half g_hh [(size_t)NTOK * Dc];
__device__ __half g_ah [(size_t)NTOK * Dc];
__device__ __half g_mh [(size_t)NTOK * DFFc];
// transposed fp16 weights [N,K]
__device__ __half g_wqkv[Lc * QKVC * Dc];
__device__ __half g_wo  [Lc * Dc * Dc];
__device__ __half g_w1  [Lc * DFFc * Dc];
__device__ __half g_w2  [Lc * Dc * DFFc];
__device__ __half g_whd [Vc * Dc];

// ------------------------- helpers ------------------------------------------
__device__ __forceinline__ uint32_t smem_u32(const void* p) {
    uint32_t a;
    asm("{ .reg .u64 t; cvta.to.shared.u64 t, %1; cvt.u32.u64 %0, t; }"
        : "=r"(a) : "l"(p));
    return a;
}
__device__ __forceinline__ void h2_store(float v0, float v1, __half* p) {
    *(__half2*)p = __floats2half2_rn(v0, v1);
}

#define LDMX4(r0, r1, r2, r3, a)                                            \
    asm volatile("ldmatrix.sync.aligned.m8n8.x4.shared.b16 {%0,%1,%2,%3}, [%4];" \
                 : "=r"(r0), "=r"(r1), "=r"(r2), "=r"(r3) : "r"(a))

#define LDMX4T(r0, r1, r2, r3, a)                                           \
    asm volatile("ldmatrix.sync.aligned.m8n8.x4.trans.shared.b16 {%0,%1,%2,%3}, [%4];" \
                 : "=r"(r0), "=r"(r1), "=r"(r2), "=r"(r3) : "r"(a))

#define MMA(d, a0, a1, a2, a3, b0v, b1v)                                    \
    asm volatile("mma.sync.aligned.m16n8k16.row.col.f32.f16.f16.f32 "       \
                 "{%0,%1,%2,%3}, {%4,%5,%6,%7}, {%8,%9}, {%0,%1,%2,%3};"    \
                 : "+f"((d)[0]), "+f"((d)[1]), "+f"((d)[2]), "+f"((d)[3])   \
                 : "r"(a0), "r"(a1), "r"(a2), "r"(a3), "r"(b0v), "r"(b1v))

#define CP_ASYNC16(dst, src)                                                \
    asm volatile("cp.async.cg.shared.global [%0], [%1], 16;"                \
                 :: "r"(dst), "l"(src))
#define CP_COMMIT() asm volatile("cp.async.commit_group;" ::: "memory")
#define CP_WAIT(n)  asm volatile("cp.async.wait_group %0;" :: "n"(n) : "memory")

// ------------------------- weight conversion --------------------------------
__global__ void convw_kernel(const float* __restrict__ W,
                             __half* __restrict__ oh, int K, int N)
{
    const size_t base = (size_t)blockIdx.y * K * N;
    int i = blockIdx.x * 256 + threadIdx.x;
    if (i >= K * N) return;
    int k = i / N, n = i % N;
    oh[base + (size_t)n * K + k] = __float2half(W[base + i]);
}

__global__ void convqkv_kernel(const float* __restrict__ Wq,
                               const float* __restrict__ Wk,
                               const float* __restrict__ Wv,
                               __half* __restrict__ oh)
{
    int i = blockIdx.x * 256 + threadIdx.x;
    const int total = Lc * Hc * Dc * HDc;
    if (i >= total) return;
    int e = i % HDc;
    int d = (i / HDc) % Dc;
    int h = (i / (HDc * Dc)) % Hc;
    int l = i / (HDc * Dc * Hc);
    int src = ((l * Hc + h) * Dc + d) * HDc + e;
    const int col = h * HDc + e;
    oh[((size_t)l * QKVC + col) * Dc + d]          = __float2half(Wq[src]);
    oh[((size_t)l * QKVC + Dc + col) * Dc + d]     = __float2half(Wk[src]);
    oh[((size_t)l * QKVC + 2 * Dc + col) * Dc + d] = __float2half(Wv[src]);
}

// ------------------------- embedding + first LN (warp / token) --------------
__global__ __launch_bounds__(256) void embed_ln_kernel(
    const int* __restrict__ idx,
    const float* __restrict__ tok, const float* __restrict__ pos,
    float* __restrict__ xout, __half* __restrict__ oh,
    const float* __restrict__ gam, const float* __restrict__ bet)
{
    const int warp = threadIdx.x >> 5;
    const int lane = threadIdx.x & 31;
    const size_t n = (size_t)blockIdx.x * 8 + warp;
    const int t = (int)(n & (Tc - 1));
    const int v = idx[n];

    const float4 tv = ((const float4*)(tok + (size_t)v * Dc))[lane];
    const float4 pv = ((const float4*)(pos + (size_t)t * Dc))[lane];
    float4 x = make_float4(tv.x + pv.x, tv.y + pv.y, tv.z + pv.z, tv.w + pv.w);
    ((float4*)(xout + n * Dc))[lane] = x;

    float s = x.x + x.y + x.z + x.w;
    #pragma unroll
    for (int o = 16; o > 0; o >>= 1) s += __shfl_xor_sync(0xffffffffu, s, o);
    const float mean = s * (1.0f / Dc);

    float4 c = make_float4(x.x - mean, x.y - mean, x.z - mean, x.w - mean);
    float q = c.x * c.x + c.y * c.y + c.z * c.z + c.w * c.w;
    #pragma unroll
    for (int o = 16; o > 0; o >>= 1) q += __shfl_xor_sync(0xffffffffu, q, o);
    const float r = rsqrtf(q * (1.0f / Dc) + 1e-5f);

    const float4 g = ((const float4*)gam)[lane];
    const float4 b = ((const float4*)bet)[lane];
    h2_store(c.x * r * g.x + b.x, c.y * r * g.y + b.y, oh + n * Dc + lane * 4);
    h2_store(c.z * r * g.z + b.z, c.w * r * g.w + b.w, oh + n * Dc + lane * 4 + 2);
}

// ------------------------- fp16 HMMA GEMM (K-chunk 64, 2-stage pipeline) ----
#define TROWB 144
#define TILEB (128 * TROWB)
#define STAGEB (2 * TILEB)
#define HGEMM_SMEM (2 * STAGEB)

__global__ __launch_bounds__(256, 2) void hgemm_kernel(
    const __half* __restrict__ A, const __half* __restrict__ B,
    const float* __restrict__ bias, const float* __restrict__ res,
    float* __restrict__ outf, __half* __restrict__ outh,
    const float* __restrict__ lnG, const float* __restrict__ lnB,
    int M, int N, int K, int relu)
{
    extern __shared__ char smem[];
    const uint32_t sb = smem_u32(smem);

    const int tid = threadIdx.x;
    const int w   = tid >> 5;
    const int l   = tid & 31;
    const int wm  = w & 1;
    const int wn  = w >> 1;
    const int m0  = blockIdx.y * 128;
    const int n0  = blockIdx.x * 128;

    const int g    = l >> 3;
    const int idx  = l & 7;
    const int lrow = (g & 1) * 8 + idx;
    const int g2   = (g >> 1) * 16;

    const uint32_t arow = (uint32_t)(wm * 64 + lrow) * TROWB + g2;
    const uint32_t brow = (uint32_t)(wn * 32 + lrow) * TROWB + g2;

    const __half* Asrc = A + (size_t)m0 * K;
    const __half* Bsrc = B + (size_t)n0 * K;

    const int nstep = K >> 6;

    auto stage = [&](int c) {
        const int ck = c << 6;
        const uint32_t base = sb + (uint32_t)(c & 1) * STAGEB;
        #pragma unroll
        for (int i = tid; i < 1024; i += 256) {
            const int r  = i >> 3;
            const int c8 = i & 7;
            CP_ASYNC16(base + r * TROWB + c8 * 16,
                       Asrc + (size_t)r * K + ck + c8 * 8);
        }
        #pragma unroll
        for (int i = tid; i < 1024; i += 256) {
            const int r  = i >> 3;
            const int c8 = i & 7;
            CP_ASYNC16(base + TILEB + r * TROWB + c8 * 16,
                       Bsrc + (size_t)r * K + ck + c8 * 8);
        }
        CP_COMMIT();
    };

    float acc[4][4][4] = {};

    stage(0);
    for (int c = 0; c < nstep; c++) {
        if (c + 1 < nstep) {
            stage(c + 1);
            CP_WAIT(1);
        } else {
            CP_WAIT(0);
        }
        __syncthreads();

        const uint32_t AHo = sb + (uint32_t)(c & 1) * STAGEB;
        const uint32_t BHo = AHo + TILEB;

        #pragma unroll
        for (int ks = 0; ks < 4; ks++) {
            const uint32_t kb = ks * 32;
            uint32_t bh_[2][4];
            #pragma unroll
            for (int p = 0; p < 2; p++) {
                const uint32_t bo = brow + p * (16 * TROWB) + kb;
                LDMX4(bh_[p][0], bh_[p][1], bh_[p][2], bh_[p][3], BHo + bo);
            }
            #pragma unroll
            for (int mt = 0; mt < 4; mt++) {
                const uint32_t ao = arow + mt * (16 * TROWB) + kb;
                uint32_t a0, a1, a2, a3;
                LDMX4(a0, a1, a2, a3, AHo + ao);
                #pragma unroll
                for (int nt = 0; nt < 4; nt++) {
                    const int p = nt >> 1, q = nt & 1;
                    MMA(acc[mt][nt], a0, a1, a2, a3, bh_[p][q], bh_[p][q + 2]);
                }
            }
        }
        __syncthreads();
    }

    const int gr = l >> 2;
    const int gc = (l & 3) * 2;

    if (lnG) {
        // ---- fused epilogue: bias + residual + LN over the 128-wide row ----
        float* sums  = (float*)smem;
        float* sumsq = (float*)smem + 512;

        #pragma unroll
        for (int mt = 0; mt < 4; mt++) {
            #pragma unroll
            for (int h = 0; h < 2; h++) {
                const int r64 = wm * 64 + mt * 16 + gr + h * 8;
                const size_t row = (size_t)m0 + r64;
                float s = 0.f, q = 0.f;
                #pragma unroll
                for (int nt = 0; nt < 4; nt++) {
                    const int n = wn * 32 + nt * 8 + gc;
                    float v0 = acc[mt][nt][h * 2];
                    float v1 = acc[mt][nt][h * 2 + 1];
                    const float2 bb = *(const float2*)(bias + n);
                    v0 += bb.x; v1 += bb.y;
                    const float2 rr = *(const float2*)(res + row * Dc + n);
                    v0 += rr.x; v1 += rr.y;
                    acc[mt][nt][h * 2]     = v0;
                    acc[mt][nt][h * 2 + 1] = v1;
                    *(float2*)(outf + row * Dc + n) = make_float2(v0, v1);
                    s += v0 + v1;
                    q += v0 * v0 + v1 * v1;
                }
                s += __shfl_xor_sync(0xffffffffu, s, 1);
                s += __shfl_xor_sync(0xffffffffu, s, 2);
                q += __shfl_xor_sync(0xffffffffu, q, 1);
                q += __shfl_xor_sync(0xffffffffu, q, 2);
                if ((l & 3) == 0) {
                    sums [r64 * 4 + wn] = s;
                    sumsq[r64 * 4 + wn] = q;
                }
            }
        }
        __syncthreads();
        #pragma unroll
        for (int mt = 0; mt < 4; mt++) {
            #pragma unroll
            for (int h = 0; h < 2; h++) {
                const int r64 = wm * 64 + mt * 16 + gr + h * 8;
                const size_t row = (size_t)m0 + r64;
                float S = sums[r64 * 4] + sums[r64 * 4 + 1]
                        + sums[r64 * 4 + 2] + sums[r64 * 4 + 3];
                float Q = sumsq[r64 * 4] + sumsq[r64 * 4 + 1]
                        + sumsq[r64 * 4 + 2] + sumsq[r64 * 4 + 3];
                const float mean = S * (1.0f / Dc);
                const float var  = Q * (1.0f / Dc) - mean * mean;
                const float rst  = rsqrtf(var + 1e-5f);
                #pragma unroll
                for (int nt = 0; nt < 4; nt++) {
                    const int n = wn * 32 + nt * 8 + gc;
                    const float2 gg = *(const float2*)(lnG + n);
                    const float2 bb = *(const float2*)(lnB + n);
                    const float v0 = acc[mt][nt][h * 2];
                    const float v1 = acc[mt][nt][h * 2 + 1];
                    h2_store((v0 - mean) * rst * gg.x + bb.x,
                             (v1 - mean) * rst * gg.y + bb.y,
                             outh + row * Dc + n);
                }
            }
        }
        return;
    }

    // ---- plain epilogue ----
    #pragma unroll
    for (int mt = 0; mt < 4; mt++) {
        #pragma unroll
        for (int h = 0; h < 2; h++) {
            const size_t row = (size_t)m0 + wm * 64 + mt * 16 + gr + h * 8;
            #pragma unroll
            for (int nt = 0; nt < 4; nt++) {
                const int n = n0 + wn * 32 + nt * 8 + gc;
                float v0 = acc[mt][nt][h * 2];
                float v1 = acc[mt][nt][h * 2 + 1];
                if (bias) {
                    const float2 bb = *(const float2*)(bias + n);
                    v0 += bb.x; v1 += bb.y;
                }
                if (relu) { v0 = fmaxf(v0, 0.f); v1 = fmaxf(v1, 0.f); }
                if (outh) {
                    h2_store(v0, v1, outh + row * N + n);
                } else {
                    *(float2*)(outf + row * N + n) = make_float2(v0, v1);
                }
            }
        }
    }
}

// ------------------------- tensor-core attention -----------------------------
// One (b,h) per 128-thread block (4 warps x 16 rows).
// S = Q@K^T via mma (fp32 accum), softmax in registers, W packed to fp16
// A-fragments directly from the C layout, O = W@V via mma with ldmatrix.trans.
#define ASTR 40   /* halves per smem row = 80B; conflict-free for ldmatrix */
__global__ __launch_bounds__(128) void attn_kernel(const __half* __restrict__ qkv,
                                                   __half* __restrict__ oh)
{
    __shared__ __half qs[Tc * ASTR];
    __shared__ __half ks[Tc * ASTR];
    __shared__ __half vs[Tc * ASTR];

    const int bh  = blockIdx.x;
    const int b   = bh >> 2;
    const int h   = bh & 3;
    const int tid = threadIdx.x;
    const int w   = tid >> 5;
    const int l   = tid & 31;

    // stage Q,K,V: 3 mats x 64 rows x 4 (16B segs) = 768 segs, 6 per thread
    for (int i = tid; i < 768; i += 128) {
        const int mat = i >> 8;
        const int r   = (i >> 2) & 63;
        const int seg = i & 3;
        const uint4 v = *(const uint4*)(qkv + ((size_t)(b * Tc + r)) * QKVC
                                        + mat * Dc + h * HDc + seg * 8);
        __half* dst = (mat == 0) ? qs : (mat == 1) ? ks : vs;
        *(uint4*)(dst + r * ASTR + seg * 8) = v;
    }
    __syncthreads();

    const uint32_t sq = smem_u32(qs);
    const uint32_t sk = smem_u32(ks);
    const uint32_t sv = smem_u32(vs);

    const int g    = l >> 3;
    const int idx  = l & 7;
    const int lrow = (g & 1) * 8 + idx;
    const int g2   = (g >> 1) * 16;        // byte offset (k-halves 0-7 / 8-15)

    // ---- phase 1: scores S[16 rows][64 cols] per warp ----
    float sc[8][4] = {};
    #pragma unroll
    for (int kt = 0; kt < 2; kt++) {
        uint32_t a0, a1, a2, a3;
        LDMX4(a0, a1, a2, a3,
              sq + (uint32_t)(16 * w + lrow) * (ASTR * 2) + kt * 32 + g2);
        #pragma unroll
        for (int p = 0; p < 4; p++) {
            uint32_t b0, b1, b2, b3;
            LDMX4(b0, b1, b2, b3,
                  sk + (uint32_t)(16 * p + lrow) * (ASTR * 2) + kt * 32 + g2);
            MMA(sc[2 * p],     a0, a1, a2, a3, b0, b2);
            MMA(sc[2 * p + 1], a0, a1, a2, a3, b1, b3);
        }
    }

    // ---- softmax (rows r0 = 16w + gr, r1 = r0 + 8) ----
    const int gr = l >> 2;
    const int c  = l & 3;
    const int r0 = 16 * w + gr;
    const int r1 = r0 + 8;
    const float scale = 0.17677669529663687f;

    float mx0 = -1e30f, mx1 = -1e30f;
    #pragma unroll
    for (int nt = 0; nt < 8; nt++) {
        #pragma unroll
        for (int j = 0; j < 2; j++) {
            const int s = nt * 8 + 2 * c + j;
            sc[nt][j]     = (s <= r0) ? sc[nt][j] * scale     : -1e30f;
            sc[nt][2 + j] = (s <= r1) ? sc[nt][2 + j] * scale : -1e30f;
            mx0 = fmaxf(mx0, sc[nt][j]);
            mx1 = fmaxf(mx1, sc[nt][2 + j]);
        }
    }
    mx0 = fmaxf(mx0, __shfl_xor_sync(0xffffffffu, mx0, 1));
    mx0 = fmaxf(mx0, __shfl_xor_sync(0xffffffffu, mx0, 2));
    mx1 = fmaxf(mx1, __shfl_xor_sync(0xffffffffu, mx1, 1));
    mx1 = fmaxf(mx1, __shfl_xor_sync(0xffffffffu, mx1, 2));

    float sum0 = 0.f, sum1 = 0.f;
    #pragma unroll
    for (int nt = 0; nt < 8; nt++) {
        #pragma unroll
        for (int j = 0; j < 2; j++) {
            const float e0 = __expf(sc[nt][j]     - mx0);   // masked -> exp(-huge)=0
            const float e1 = __expf(sc[nt][2 + j] - mx1);
            sc[nt][j]     = e0;
            sc[nt][2 + j] = e1;
            sum0 += e0;
            sum1 += e1;
        }
    }
    sum0 += __shfl_xor_sync(0xffffffffu, sum0, 1);
    sum0 += __shfl_xor_sync(0xffffffffu, sum0, 2);
    sum1 += __shfl_xor_sync(0xffffffffu, sum1, 1);
    sum1 += __shfl_xor_sync(0xffffffffu, sum1, 2);
    const float inv0 = 1.f / sum0;
    const float inv1 = 1.f / sum1;

    // pack normalized weights into fp16 A-fragments (4 k-chunks of 16)
    uint32_t aw[4][4];
    #pragma unroll
    for (int kt = 0; kt < 4; kt++) {
        aw[kt][0] = __half2_raw(__floats2half2_rn(sc[2*kt][0]   * inv0, sc[2*kt][1]   * inv0)).x
                  | ((uint32_t)__half2_raw(__floats2half2_rn(sc[2*kt][0] * inv0, sc[2*kt][1] * inv0)).y << 16);
        // (simple form below; the above is replaced by direct reinterpret)
    }
    #pragma unroll
    for (int kt = 0; kt < 4; kt++) {
        __half2 p0 = __floats2half2_rn(sc[2*kt][0]     * inv0, sc[2*kt][1]     * inv0);
        __half2 p1 = __floats2half2_rn(sc[2*kt][2]     * inv1, sc[2*kt][3]     * inv1);
        __half2 p2 = __floats2half2_rn(sc[2*kt+1][0]   * inv0, sc[2*kt+1][1]   * inv0);
        __half2 p3 = __floats2half2_rn(sc[2*kt+1][2]   * inv1, sc[2*kt+1][3]   * inv1);
        aw[kt][0] = *(uint32_t*)&p0;
        aw[kt][1] = *(uint32_t*)&p1;
        aw[kt][2] = *(uint32_t*)&p2;
        aw[kt][3] = *(uint32_t*)&p3;
    }

    // ---- phase 2: O[16 rows][32] = W @ V ----
    float o[4][4] = {};
    #pragma unroll
    for (int kt = 0; kt < 4; kt++) {
        #pragma unroll
        for (int pn = 0; pn < 2; pn++) {
            uint32_t r0v, r1v, r2v, r3v;
            LDMX4T(r0v, r1v, r2v, r3v,
                   sv + (uint32_t)(16 * kt + lrow) * (ASTR * 2) + pn * 32 + g2);
            MMA(o[pn * 2],     aw[kt][0], aw[kt][1], aw[kt][2], aw[kt][3], r0v, r1v);
            MMA(o[pn * 2 + 1], aw[kt][0], aw[kt][1], aw[kt][2], aw[kt][3], r2v, r3v);
        }
    }

    // ---- write output (fp16) ----
    #pragma unroll
    for (int nt = 0; nt < 4; nt++) {
        const int col = h * HDc + nt * 8 + 2 * c;
        h2_store(o[nt][0], o[nt][1], oh + ((size_t)(b * Tc + r0)) * Dc + col);
        h2_store(o[nt][2], o[nt][3], oh + ((size_t)(b * Tc + r1)) * Dc + col);
    }
}

// ------------------------- launcher -----------------------------------------
extern "C" void kernel_launch(void* const* d_in, const int* in_sizes, int n_in,
                              void* d_out, int out_size)
{
    (void)in_sizes; (void)n_in; (void)out_size;
    const int*   idx  = (const int*)  d_in[0];
    const float* tok  = (const float*)d_in[1];
    const float* pos  = (const float*)d_in[2];
    const float* Wq   = (const float*)d_in[3];
    const float* Wk   = (const float*)d_in[4];
    const float* Wv   = (const float*)d_in[5];
    const float* Wo   = (const float*)d_in[6];
    const float* bo   = (const float*)d_in[7];
    const float* ln1g = (const float*)d_in[8];
    const float* ln1b = (const float*)d_in[9];
    const float* W1   = (const float*)d_in[10];
    const float* b1   = (const float*)d_in[11];
    const float* W2   = (const float*)d_in[12];
    const float* b2   = (const float*)d_in[13];
    const float* ln2g = (const float*)d_in[14];
    const float* ln2b = (const float*)d_in[15];
    const float* lnfg = (const float*)d_in[16];
    const float* lnfb = (const float*)d_in[17];
    const float* Wh   = (const float*)d_in[18];
    const float* bhd  = (const float*)d_in[19];
    float* out = (float*)d_out;

    float *x;
    __half *qkvh, *hh, *ah, *mh, *wq, *wo, *w1, *w2, *whd;
    cudaGetSymbolAddress((void**)&x,    g_x);
    cudaGetSymbolAddress((void**)&qkvh, g_qkv);
    cudaGetSymbolAddress((void**)&hh,   g_hh);
    cudaGetSymbolAddress((void**)&ah,   g_ah);
    cudaGetSymbolAddress((void**)&mh,   g_mh);
    cudaGetSymbolAddress((void**)&wq,   g_wqkv);
    cudaGetSymbolAddress((void**)&wo,   g_wo);
    cudaGetSymbolAddress((void**)&w1,   g_w1);
    cudaGetSymbolAddress((void**)&w2,   g_w2);
    cudaGetSymbolAddress((void**)&whd,  g_whd);

    cudaFuncSetAttribute(hgemm_kernel,
                         cudaFuncAttributeMaxDynamicSharedMemorySize, HGEMM_SMEM);

    const int MT = NTOK / 128;
    const dim3 gQKV(QKVC / 128, MT);
    const dim3 gD  (1,          MT);
    const dim3 gFF (DFFc / 128, MT);
    const dim3 gV  (Vc   / 128, MT);

    // interleaved launch order keeps an hgemm / attn in the ncu window (-s 5)
    convqkv_kernel<<<(Lc * Hc * Dc * HDc + 255) / 256, 256>>>(Wq, Wk, Wv, wq);        // 0
    embed_ln_kernel<<<NTOK / 8, 256>>>(idx, tok, pos, x, hh, ln1g, ln1b);             // 1
    hgemm_kernel<<<gQKV, 256, HGEMM_SMEM>>>(                                          // 2
        hh, wq, nullptr, nullptr, nullptr, qkvh, nullptr, nullptr,
        NTOK, QKVC, Dc, 0);
    attn_kernel<<<Bc * Hc, 128>>>(qkvh, ah);                                          // 3
    convw_kernel<<<dim3((Dc * Dc + 255) / 256, Lc), 256>>>(Wo, wo, Dc, Dc);           // 4
    hgemm_kernel<<<gD, 256, HGEMM_SMEM>>>(                                            // 5
        ah, wo, bo, x, x, hh, ln2g, ln2b, NTOK, Dc, Dc, 0);
    convw_kernel<<<dim3((Dc * DFFc + 255) / 256, Lc), 256>>>(W1, w1, Dc, DFFc);       // 6
    hgemm_kernel<<<gFF, 256, HGEMM_SMEM>>>(                                           // 7
        hh, w1, b1, nullptr, nullptr, mh, nullptr, nullptr, NTOK, DFFc, Dc, 1);
    convw_kernel<<<dim3((DFFc * Dc + 255) / 256, Lc), 256>>>(W2, w2, DFFc, Dc);       // 8
    hgemm_kernel<<<gD, 256, HGEMM_SMEM>>>(                                            // 9
        mh, w2, b2, x, x, hh, ln1g + Dc, ln1b + Dc, NTOK, Dc, DFFc, 0);
    convw_kernel<<<dim3((Dc * Vc + 255) / 256, 1), 256>>>(Wh, whd, Dc, Vc);           // 10

    for (int l = 1; l < Lc; l++) {
        hgemm_kernel<<<gQKV, 256, HGEMM_SMEM>>>(
            hh, wq + (size_t)l * QKVC * Dc,
            nullptr, nullptr, nullptr, qkvh, nullptr, nullptr,
            NTOK, QKVC, Dc, 0);
        attn_kernel<<<Bc * Hc, 128>>>(qkvh, ah);
        hgemm_kernel<<<gD, 256, HGEMM_SMEM>>>(
            ah, wo + (size_t)l * Dc * Dc,
            bo + l * Dc, x, x, hh, ln2g + l * Dc, ln2b + l * Dc,
            NTOK, Dc, Dc, 0);
        hgemm_kernel<<<gFF, 256, HGEMM_SMEM>>>(
            hh, w1 + (size_t)l * DFFc * Dc,
            b1 + l * DFFc, nullptr, nullptr, mh, nullptr, nullptr,
            NTOK, DFFc, Dc, 1);
        const float* ng = (l < Lc - 1) ? (ln1g + (l + 1) * Dc) : lnfg;
        const float* nb = (l < Lc - 1) ? (ln1b + (l + 1) * Dc) : lnfb;
        hgemm_kernel<<<gD, 256, HGEMM_SMEM>>>(
            mh, w2 + (size_t)l * Dc * DFFc,
            b2 + l * Dc, x, x, hh, ng, nb,
            NTOK, Dc, DFFc, 0);
    }

    hgemm_kernel<<<gV, 256, HGEMM_SMEM>>>(
        hh, whd, bhd, nullptr, out, nullptr, nullptr, nullptr,
        NTOK, Vc, Dc, 0);
}